// round 1
// baseline (speedup 1.0000x reference)
#include <cuda_runtime.h>
#include <math.h>
#include <stdint.h>

#define E_EDGES   1500000
#define N_ENT     200000
#define N_ITEMS   100000
#define DIM       64
#define K_EDGES   256
#define K_ITEMS   100
#define NBINS     8192
#define BIN_SHIFT 19
#define MAXC      65536

// scale = 1 / (2 * sqrt(32)) : per-head 1/sqrt(Dk) then mean over 2 heads
#define LOGIT_SCALE 0.08838834764831845f

// ---------------- scratch (device globals; no allocation allowed) ----------
__device__ float    g_proj[(size_t)N_ENT * DIM];   // 51.2 MB
__device__ float    g_logit[E_EDGES];              // 6 MB
__device__ unsigned g_enc[E_EDGES];                // 6 MB (monotone-encoded noisy score)
__device__ unsigned g_segmax[N_ENT];               // encoded per-head max
__device__ float    g_denom[N_ENT];
__device__ float    g_deg[N_ENT];
__device__ float    g_sumnode[N_ENT];
__device__ unsigned g_hist_e[NBINS];
__device__ unsigned g_hist_i[NBINS];
__device__ unsigned g_thresh[2];
__device__ unsigned g_cnt[2];
__device__ float    g_candv_e[MAXC];
__device__ int      g_candi_e[MAXC];
__device__ float    g_candv_i[MAXC];
__device__ int      g_candi_i[MAXC];

// ------------- monotone float<->uint encoding (order-preserving) ----------
__device__ __forceinline__ unsigned enc_f(float f) {
    unsigned u = __float_as_uint(f);
    return u ^ ((unsigned)(((int)u) >> 31) | 0x80000000u);
}
__device__ __forceinline__ float dec_f(unsigned e) {
    unsigned u = (e & 0x80000000u) ? (e ^ 0x80000000u) : ~e;
    return __uint_as_float(u);
}

// --------------------------- kernels --------------------------------------

__global__ void zero_kernel() {
    int i = blockIdx.x * blockDim.x + threadIdx.x;
    if (i < N_ENT) {
        g_segmax[i] = 0u;      // encodes below every non-NaN float
        g_denom[i]  = 0.f;
        g_deg[i]    = 0.f;
        g_sumnode[i]= 0.f;
    }
    if (i < NBINS) { g_hist_e[i] = 0u; g_hist_i[i] = 0u; }
    if (i < 2)     { g_cnt[i] = 0u; }
}

// proj = emb @ W : block = 256 threads -> 32 rows, 8 threads/row, 8 cols/thread
__global__ void proj_kernel(const float* __restrict__ emb,
                            const float* __restrict__ W) {
    __shared__ __align__(16) float sW[DIM * DIM];   // 16 KB
    __shared__ float sE[32 * 65];                   // padded rows (bank-safe)
    int tid = threadIdx.x;
    int rowBase = blockIdx.x * 32;

    // cooperative loads
    for (int i = tid; i < (DIM * DIM) / 4; i += 256)
        ((float4*)sW)[i] = ((const float4*)W)[i];
    for (int i = tid; i < 32 * DIM; i += 256) {
        int r = i >> 6, c = i & 63;
        sE[r * 65 + c] = emb[(size_t)(rowBase + r) * DIM + c];
    }
    __syncthreads();

    int lrow = tid >> 3;
    int c0   = (tid & 7) * 8;
    float acc[8];
#pragma unroll
    for (int j = 0; j < 8; j++) acc[j] = 0.f;

#pragma unroll
    for (int k = 0; k < DIM; k++) {
        float e = sE[lrow * 65 + k];
        const float* wr = &sW[k * DIM + c0];
#pragma unroll
        for (int j = 0; j < 8; j++) acc[j] = fmaf(e, wr[j], acc[j]);
    }

    float* dst = &g_proj[(size_t)(rowBase + lrow) * DIM + c0];
#pragma unroll
    for (int j = 0; j < 8; j++) dst[j] = acc[j];
}

// warp per edge: logit + seg-max + node sums + degree
__global__ void edge_kernel(const int* __restrict__ eidx,
                            const int* __restrict__ etype,
                            const float* __restrict__ rel) {
    int gw = (blockIdx.x * blockDim.x + threadIdx.x) >> 5;
    if (gw >= E_EDGES) return;
    int lane = threadIdx.x & 31;

    int h = eidx[gw];
    int t = eidx[E_EDGES + gw];
    int r = etype[gw] - 1;

    float2 a = ((const float2*)(g_proj + (size_t)h * DIM))[lane];
    float2 b = ((const float2*)(g_proj + (size_t)t * DIM))[lane];
    float2 c = ((const float2*)(rel    + (size_t)r * DIM))[lane];

    float s = a.x * b.x * c.x + a.y * b.y * c.y;
#pragma unroll
    for (int o = 16; o; o >>= 1) s += __shfl_xor_sync(0xffffffffu, s, o);

    if (lane == 0) {
        float logit = s * LOGIT_SCALE;
        g_logit[gw] = logit;
        atomicMax(&g_segmax[h], enc_f(logit));
        atomicAdd(&g_sumnode[h], logit);
        atomicAdd(&g_sumnode[t], logit);
        atomicAdd(&g_deg[h], 1.0f);
    }
}

// softmax denominator (needs completed seg-max)
__global__ void denom_kernel(const int* __restrict__ head) {
    int e = blockIdx.x * blockDim.x + threadIdx.x;
    if (e >= E_EDGES) return;
    int h = head[e];
    float m = dec_f(g_segmax[h]);
    atomicAdd(&g_denom[h], expf(g_logit[e] - m));
}

// score + gumbel noise + encoded-value histogram (shared-privatized)
__global__ void score_kernel(const int* __restrict__ head,
                             const float* __restrict__ noise,
                             float* __restrict__ out) {
    __shared__ unsigned sh[NBINS];   // 32 KB
    for (int i = threadIdx.x; i < NBINS; i += blockDim.x) sh[i] = 0u;
    __syncthreads();

    for (int e = blockIdx.x * blockDim.x + threadIdx.x; e < E_EDGES;
         e += gridDim.x * blockDim.x) {
        int h = head[e];
        float m  = dec_f(g_segmax[h]);
        float sc = expf(g_logit[e] - m) / g_denom[h] * g_deg[h];
        out[e] = sc;
        float gum = -logf(-logf(noise[e]));
        unsigned en = enc_f(sc + gum);
        g_enc[e] = en;
        atomicAdd(&sh[en >> BIN_SHIFT], 1u);
    }
    __syncthreads();
    for (int i = threadIdx.x; i < NBINS; i += blockDim.x) {
        unsigned v = sh[i];
        if (v) atomicAdd(&g_hist_e[i], v);
    }
}

// histogram of item sums (first N_ITEMS nodes)
__global__ void itemhist_kernel() {
    __shared__ unsigned sh[NBINS];
    for (int i = threadIdx.x; i < NBINS; i += blockDim.x) sh[i] = 0u;
    __syncthreads();
    for (int i = blockIdx.x * blockDim.x + threadIdx.x; i < N_ITEMS;
         i += gridDim.x * blockDim.x) {
        atomicAdd(&sh[enc_f(g_sumnode[i]) >> BIN_SHIFT], 1u);
    }
    __syncthreads();
    for (int i = threadIdx.x; i < NBINS; i += blockDim.x) {
        unsigned v = sh[i];
        if (v) atomicAdd(&g_hist_i[i], v);
    }
}

// single block: suffix-scan both histograms, emit bin-floor thresholds
__global__ void thresh_kernel() {
    __shared__ unsigned chunk[1024];
    __shared__ unsigned super[32];
    for (int task = 0; task < 2; task++) {
        const unsigned* hist = task ? g_hist_i : g_hist_e;
        unsigned K = task ? K_ITEMS : K_EDGES;
        unsigned s = 0;
        int base = threadIdx.x * 8;
#pragma unroll
        for (int j = 0; j < 8; j++) s += hist[base + j];
        chunk[threadIdx.x] = s;
        __syncthreads();
        if (threadIdx.x < 32) {
            unsigned ss = 0;
            for (int j = 0; j < 32; j++) ss += chunk[threadIdx.x * 32 + j];
            super[threadIdx.x] = ss;
        }
        __syncthreads();
        if (threadIdx.x == 0) {
            unsigned cum = 0;
            int sIdx = 31;
            while (sIdx > 0 && cum + super[sIdx] < K) { cum += super[sIdx]; sIdx--; }
            int cIdx = sIdx * 32 + 31;
            while (cIdx > 0 && cum + chunk[cIdx] < K) { cum += chunk[cIdx]; cIdx--; }
            int b = cIdx * 8 + 7;
            while (b > 0 && cum + hist[b] < K) { cum += hist[b]; b--; }
            g_thresh[task] = ((unsigned)b) << BIN_SHIFT;
        }
        __syncthreads();
    }
}

__global__ void collect_edges_kernel() {
    int e = blockIdx.x * blockDim.x + threadIdx.x;
    if (e >= E_EDGES) return;
    unsigned en = g_enc[e];
    if (en >= g_thresh[0]) {
        unsigned pos = atomicAdd(&g_cnt[0], 1u);
        if (pos < MAXC) { g_candv_e[pos] = dec_f(en); g_candi_e[pos] = e; }
    }
}

__global__ void collect_items_kernel() {
    int i = blockIdx.x * blockDim.x + threadIdx.x;
    if (i >= N_ITEMS) return;
    float v = g_sumnode[i];
    if (enc_f(v) >= g_thresh[1]) {
        unsigned pos = atomicAdd(&g_cnt[1], 1u);
        if (pos < MAXC) { g_candv_i[pos] = v; g_candi_i[pos] = i; }
    }
}

// 2 blocks: blockIdx.x = task. Exact rank placement (value desc, index asc).
__global__ void rank_kernel(float* __restrict__ out) {
    int task = blockIdx.x;
    const float* cv = task ? g_candv_i : g_candv_e;
    const int*   ci = task ? g_candi_i : g_candi_e;
    int C = (int)min(g_cnt[task], (unsigned)MAXC);
    int K = task ? K_ITEMS : K_EDGES;
    float* outV = task ? (out + E_EDGES + 2 * K_EDGES) : (out + E_EDGES);
    float* outI = outV + K;

    for (int i = threadIdx.x; i < C; i += blockDim.x) {
        float vi = cv[i];
        int   ii = ci[i];
        int rank = 0;
        for (int j = 0; j < C; j++) {
            float vj = cv[j];
            int   ij = ci[j];
            rank += (vj > vi) || (vj == vi && ij < ii);
        }
        if (rank < K) { outV[rank] = vi; outI[rank] = (float)ii; }
    }
}

// --------------------------- launch ---------------------------------------
extern "C" void kernel_launch(void* const* d_in, const int* in_sizes, int n_in,
                              void* d_out, int out_size) {
    const float* entity_emb  = (const float*)d_in[0];
    const float* W_Q         = (const float*)d_in[1];
    const float* relation    = (const float*)d_in[2];
    const float* noise_u     = (const float*)d_in[3];
    const int*   edge_index  = (const int*)d_in[4];
    const int*   edge_type   = (const int*)d_in[5];
    float* out = (float*)d_out;

    const int* head = edge_index;  // [0..E): head, [E..2E): tail

    zero_kernel<<<(N_ENT + 255) / 256, 256>>>();
    proj_kernel<<<N_ENT / 32, 256>>>(entity_emb, W_Q);
    edge_kernel<<<(E_EDGES * 32 + 255) / 256, 256>>>(edge_index, edge_type, relation);
    denom_kernel<<<(E_EDGES + 255) / 256, 256>>>(head);
    score_kernel<<<296, 256>>>(head, noise_u, out);
    itemhist_kernel<<<64, 256>>>();
    thresh_kernel<<<1, 1024>>>();
    collect_edges_kernel<<<(E_EDGES + 255) / 256, 256>>>();
    collect_items_kernel<<<(N_ITEMS + 255) / 256, 256>>>();
    rank_kernel<<<2, 1024>>>(out);
}

// round 6
// speedup vs baseline: 1.5831x; 1.5831x over previous
#include <cuda_runtime.h>
#include <math.h>
#include <stdint.h>

#define E_EDGES   1500000
#define N_ENT     200000
#define N_ITEMS   100000
#define DIM       64
#define K_EDGES   256
#define K_ITEMS   100
#define NBINS     8192
#define BIN_SHIFT 19
#define MAXC      65536

// scale = 1 / (2 * sqrt(32)) : per-head 1/sqrt(Dk) then mean over 2 heads
#define LOGIT_SCALE 0.08838834764831845f

// ---------------- scratch (device globals; no allocation allowed) ----------
__device__ float    g_proj[(size_t)N_ENT * DIM];   // 51.2 MB (L2-resident)
__device__ float    g_logit[E_EDGES];              // 6 MB
__device__ unsigned g_enc[E_EDGES];                // 6 MB
__device__ float2   g_nd[N_ENT];                   // {denom, deg}
__device__ float    g_sumnode[N_ENT];
__device__ unsigned g_hist_e[NBINS];
__device__ unsigned g_hist_i[NBINS];
__device__ unsigned g_thresh[2];
__device__ unsigned g_cnt[2];
__device__ float    g_candv_e[MAXC];
__device__ int      g_candi_e[MAXC];
__device__ float    g_candv_i[MAXC];
__device__ int      g_candi_i[MAXC];

// ------------- monotone float<->uint encoding (order-preserving) ----------
__device__ __forceinline__ unsigned enc_f(float f) {
    unsigned u = __float_as_uint(f);
    return u ^ ((unsigned)(((int)u) >> 31) | 0x80000000u);
}
__device__ __forceinline__ float dec_f(unsigned e) {
    unsigned u = (e & 0x80000000u) ? (e ^ 0x80000000u) : ~e;
    return __uint_as_float(u);
}

// packed f32x2 fma: d = a*b + d (both halves)
__device__ __forceinline__ void fma2(unsigned long long& d,
                                     unsigned long long a,
                                     unsigned long long b) {
    asm("fma.rn.f32x2 %0, %1, %2, %0;" : "+l"(d) : "l"(a), "l"(b));
}
__device__ __forceinline__ unsigned long long dup2(float x) {
    unsigned long long r;
    unsigned u = __float_as_uint(x);
    asm("mov.b64 %0, {%1, %1};" : "=l"(r) : "r"(u));
    return r;
}
__device__ __forceinline__ float2 unpk(unsigned long long v) {
    unsigned lo, hi;
    asm("mov.b64 {%0, %1}, %2;" : "=r"(lo), "=r"(hi) : "l"(v));
    return make_float2(__uint_as_float(lo), __uint_as_float(hi));
}

// --------------------------- kernels --------------------------------------

__global__ void zero_kernel() {
    int i = blockIdx.x * blockDim.x + threadIdx.x;
    if (i < N_ENT) {
        g_nd[i]      = make_float2(0.f, 0.f);
        g_sumnode[i] = 0.f;
    }
    if (i < NBINS) { g_hist_e[i] = 0u; g_hist_i[i] = 0u; }
    if (i < 2)     { g_cnt[i] = 0u; }
}

// proj = emb @ W : 256 threads -> 64 rows, 4 threads/row, 16 cols/thread
__global__ void proj_kernel(const float* __restrict__ emb,
                            const float* __restrict__ W) {
    __shared__ __align__(16) float sW[DIM * DIM];   // 16 KB, row k contiguous
    __shared__ float sE[64 * 65];                   // padded (bank-safe bcast)
    int tid = threadIdx.x;
    size_t rowBase = (size_t)blockIdx.x * 64;

    for (int i = tid; i < (DIM * DIM) / 4; i += 256)
        ((float4*)sW)[i] = ((const float4*)W)[i];
    for (int i = tid; i < (64 * DIM) / 4; i += 256) {
        float4 v = ((const float4*)(emb + rowBase * DIM))[i];
        int r = i >> 4, c = (i & 15) * 4;
        float* d = &sE[r * 65 + c];
        d[0] = v.x; d[1] = v.y; d[2] = v.z; d[3] = v.w;
    }
    __syncthreads();

    int lrow = tid >> 2;            // 0..63
    int q    = (tid & 3) * 4;       // float4-index base (16 floats)
    unsigned long long acc[8];
#pragma unroll
    for (int j = 0; j < 8; j++) acc[j] = 0ull;

    const ulonglong2* sWu = (const ulonglong2*)sW;  // 16 ull2 per k-row
#pragma unroll
    for (int k = 0; k < DIM; k++) {
        unsigned long long e2 = dup2(sE[lrow * 65 + k]);
#pragma unroll
        for (int j = 0; j < 4; j++) {
            ulonglong2 w = sWu[k * 16 + q + j];
            fma2(acc[2 * j],     e2, w.x);
            fma2(acc[2 * j + 1], e2, w.y);
        }
    }

    float* dst = &g_proj[(rowBase + lrow) * DIM + q * 4];
#pragma unroll
    for (int j = 0; j < 4; j++) {
        float2 lo = unpk(acc[2 * j]);
        float2 hi = unpk(acc[2 * j + 1]);
        ((float4*)dst)[j] = make_float4(lo.x, lo.y, hi.x, hi.y);
    }
}

// 8 lanes per edge: logit + fused denom/deg + node logit sums
__global__ void edge_kernel(const int* __restrict__ eidx,
                            const int* __restrict__ etype,
                            const float* __restrict__ rel) {
    int idx = blockIdx.x * blockDim.x + threadIdx.x;
    int e = idx >> 3;
    if (e >= E_EDGES) return;
    int sub = idx & 7;

    int h = __ldg(eidx + e);
    int t = __ldg(eidx + E_EDGES + e);
    int r = __ldg(etype + e) - 1;

    const float4* pa = (const float4*)(g_proj + (size_t)h * DIM);
    const float4* pb = (const float4*)(g_proj + (size_t)t * DIM);
    const float4* pc = (const float4*)(rel    + (size_t)r * DIM);

    float4 a0 = pa[sub],     b0 = pb[sub],     c0 = pc[sub];
    float4 a1 = pa[sub + 8], b1 = pb[sub + 8], c1 = pc[sub + 8];

    float s = a0.x * b0.x * c0.x + a0.y * b0.y * c0.y
            + a0.z * b0.z * c0.z + a0.w * b0.w * c0.w
            + a1.x * b1.x * c1.x + a1.y * b1.y * c1.y
            + a1.z * b1.z * c1.z + a1.w * b1.w * c1.w;

    s += __shfl_xor_sync(0xffffffffu, s, 4);
    s += __shfl_xor_sync(0xffffffffu, s, 2);
    s += __shfl_xor_sync(0xffffffffu, s, 1);

    if (sub == 0) {
        float logit = s * LOGIT_SCALE;
        g_logit[e] = logit;
        atomicAdd(&g_nd[h].x, __expf(logit));   // softmax denominator (no max)
        atomicAdd(&g_nd[h].y, 1.0f);            // degree
        atomicAdd(&g_sumnode[h], logit);
        atomicAdd(&g_sumnode[t], logit);
    }
}

// score + gumbel noise + encoded-value histogram (shared-privatized)
__global__ void score_kernel(const int* __restrict__ head,
                             const float* __restrict__ noise,
                             float* __restrict__ out) {
    __shared__ unsigned sh[NBINS];   // 32 KB
    for (int i = threadIdx.x; i < NBINS; i += blockDim.x) sh[i] = 0u;
    __syncthreads();

    for (int e = blockIdx.x * blockDim.x + threadIdx.x; e < E_EDGES;
         e += gridDim.x * blockDim.x) {
        int h = head[e];
        float2 dd = g_nd[h];
        float sc = __expf(g_logit[e]) / dd.x * dd.y;
        out[e] = sc;
        // inner log MUST be accurate: u ~ 1-1e-4 for top-k edges and __logf's
        // abs error would be ~0.3% relative there (comparable to the rank-256
        // order-statistic gap). Outer fast log is safe (~1e-6 abs on gumbel).
        float inner = -logf(noise[e]);
        float gum = -__logf(inner);
        unsigned en = enc_f(sc + gum);
        g_enc[e] = en;
        atomicAdd(&sh[en >> BIN_SHIFT], 1u);
    }
    __syncthreads();
    for (int i = threadIdx.x; i < NBINS; i += blockDim.x) {
        unsigned v = sh[i];
        if (v) atomicAdd(&g_hist_e[i], v);
    }
}

// histogram of item sums (first N_ITEMS nodes)
__global__ void itemhist_kernel() {
    __shared__ unsigned sh[NBINS];
    for (int i = threadIdx.x; i < NBINS; i += blockDim.x) sh[i] = 0u;
    __syncthreads();
    for (int i = blockIdx.x * blockDim.x + threadIdx.x; i < N_ITEMS;
         i += gridDim.x * blockDim.x) {
        atomicAdd(&sh[enc_f(g_sumnode[i]) >> BIN_SHIFT], 1u);
    }
    __syncthreads();
    for (int i = threadIdx.x; i < NBINS; i += blockDim.x) {
        unsigned v = sh[i];
        if (v) atomicAdd(&g_hist_i[i], v);
    }
}

// single block: suffix-scan both histograms, emit bin-floor thresholds
__global__ void thresh_kernel() {
    __shared__ unsigned chunk[1024];
    __shared__ unsigned super[32];
    for (int task = 0; task < 2; task++) {
        const unsigned* hist = task ? g_hist_i : g_hist_e;
        unsigned K = task ? K_ITEMS : K_EDGES;
        unsigned s = 0;
        int base = threadIdx.x * 8;
#pragma unroll
        for (int j = 0; j < 8; j++) s += hist[base + j];
        chunk[threadIdx.x] = s;
        __syncthreads();
        if (threadIdx.x < 32) {
            unsigned ss = 0;
            for (int j = 0; j < 32; j++) ss += chunk[threadIdx.x * 32 + j];
            super[threadIdx.x] = ss;
        }
        __syncthreads();
        if (threadIdx.x == 0) {
            unsigned cum = 0;
            int sIdx = 31;
            while (sIdx > 0 && cum + super[sIdx] < K) { cum += super[sIdx]; sIdx--; }
            int cIdx = sIdx * 32 + 31;
            while (cIdx > 0 && cum + chunk[cIdx] < K) { cum += chunk[cIdx]; cIdx--; }
            int b = cIdx * 8 + 7;
            while (b > 0 && cum + hist[b] < K) { cum += hist[b]; b--; }
            g_thresh[task] = ((unsigned)b) << BIN_SHIFT;
        }
        __syncthreads();
    }
}

__global__ void collect_edges_kernel() {
    int e = blockIdx.x * blockDim.x + threadIdx.x;
    if (e >= E_EDGES) return;
    unsigned en = g_enc[e];
    if (en >= g_thresh[0]) {
        unsigned pos = atomicAdd(&g_cnt[0], 1u);
        if (pos < MAXC) { g_candv_e[pos] = dec_f(en); g_candi_e[pos] = e; }
    }
}

__global__ void collect_items_kernel() {
    int i = blockIdx.x * blockDim.x + threadIdx.x;
    if (i >= N_ITEMS) return;
    float v = g_sumnode[i];
    if (enc_f(v) >= g_thresh[1]) {
        unsigned pos = atomicAdd(&g_cnt[1], 1u);
        if (pos < MAXC) { g_candv_i[pos] = v; g_candi_i[pos] = i; }
    }
}

// 2 blocks: blockIdx.x = task. Exact rank placement (value desc, index asc).
__global__ void rank_kernel(float* __restrict__ out) {
    int task = blockIdx.x;
    const float* cv = task ? g_candv_i : g_candv_e;
    const int*   ci = task ? g_candi_i : g_candi_e;
    int C = (int)min(g_cnt[task], (unsigned)MAXC);
    int K = task ? K_ITEMS : K_EDGES;
    float* outV = task ? (out + E_EDGES + 2 * K_EDGES) : (out + E_EDGES);
    float* outI = outV + K;

    for (int i = threadIdx.x; i < C; i += blockDim.x) {
        float vi = cv[i];
        int   ii = ci[i];
        int rank = 0;
        for (int j = 0; j < C; j++) {
            float vj = cv[j];
            int   ij = ci[j];
            rank += (vj > vi) || (vj == vi && ij < ii);
        }
        if (rank < K) { outV[rank] = vi; outI[rank] = (float)ii; }
    }
}

// --------------------------- launch ---------------------------------------
extern "C" void kernel_launch(void* const* d_in, const int* in_sizes, int n_in,
                              void* d_out, int out_size) {
    const float* entity_emb  = (const float*)d_in[0];
    const float* W_Q         = (const float*)d_in[1];
    const float* relation    = (const float*)d_in[2];
    const float* noise_u     = (const float*)d_in[3];
    const int*   edge_index  = (const int*)d_in[4];
    const int*   edge_type   = (const int*)d_in[5];
    float* out = (float*)d_out;

    const int* head = edge_index;  // [0..E): head, [E..2E): tail

    zero_kernel<<<(N_ENT + 255) / 256, 256>>>();
    proj_kernel<<<N_ENT / 64, 256>>>(entity_emb, W_Q);
    edge_kernel<<<(E_EDGES * 8 + 255) / 256, 256>>>(edge_index, edge_type, relation);
    itemhist_kernel<<<64, 256>>>();
    score_kernel<<<592, 256>>>(head, noise_u, out);
    thresh_kernel<<<1, 1024>>>();
    collect_edges_kernel<<<(E_EDGES + 255) / 256, 256>>>();
    collect_items_kernel<<<(N_ITEMS + 255) / 256, 256>>>();
    rank_kernel<<<2, 1024>>>(out);
}